// round 1
// baseline (speedup 1.0000x reference)
#include <cuda_runtime.h>
#include <cstdint>

#define NROWS 50000
#define NFEAT 512
#define HID   128
#define NEDGE 1600000

// ------------------------- scratch (device globals) -------------------------
__device__ float g_xw[(size_t)NROWS * HID];          // x @ W1            25.6 MB
__device__ float g_hw[(size_t)NROWS * NFEAT];        // h @ W2           102.4 MB
__device__ int   g_col1[NEDGE];
__device__ float g_val1[NEDGE];
__device__ int   g_rs1[NROWS + 1];
__device__ int   g_col2[NEDGE];
__device__ float g_val2[NEDGE];
__device__ int   g_rs2[NROWS + 1];
__device__ int   g_cnt[NROWS];
__device__ int   g_next[NROWS];

// ------------------------------ CSR build -----------------------------------
__global__ void k_zero_int(int* p, int n) {
    int i = blockIdx.x * blockDim.x + threadIdx.x;
    if (i < n) p[i] = 0;
}

__global__ void k_hist(const int* __restrict__ row, int* __restrict__ cnt) {
    int e = blockIdx.x * blockDim.x + threadIdx.x;
    if (e < NEDGE) atomicAdd(&cnt[row[e]], 1);
}

// single-block exclusive scan over n counters; writes rs[0..n], rs[n] = total
__global__ void k_scan(const int* __restrict__ cnt, int* __restrict__ rs, int n) {
    __shared__ int temp[1024];
    __shared__ int carry;
    if (threadIdx.x == 0) carry = 0;
    __syncthreads();
    for (int base = 0; base < n; base += 1024) {
        int i = base + (int)threadIdx.x;
        int v = (i < n) ? cnt[i] : 0;
        temp[threadIdx.x] = v;
        __syncthreads();
        #pragma unroll
        for (int off = 1; off < 1024; off <<= 1) {
            int t = (threadIdx.x >= (unsigned)off) ? temp[threadIdx.x - off] : 0;
            __syncthreads();
            temp[threadIdx.x] += t;
            __syncthreads();
        }
        if (i < n) rs[i] = carry + temp[threadIdx.x] - v;   // exclusive
        __syncthreads();
        if (threadIdx.x == 0) carry += temp[1023];
        __syncthreads();
    }
    if (threadIdx.x == 0) rs[n] = carry;
}

__global__ void k_copy_int(const int* __restrict__ a, int* __restrict__ b, int n) {
    int i = blockIdx.x * blockDim.x + threadIdx.x;
    if (i < n) b[i] = a[i];
}

__global__ void k_scatter(const int* __restrict__ row, const int* __restrict__ col,
                          const float* __restrict__ val, int* __restrict__ next,
                          int* __restrict__ oc, float* __restrict__ ov) {
    int e = blockIdx.x * blockDim.x + threadIdx.x;
    if (e < NEDGE) {
        int r = row[e];
        int p = atomicAdd(&next[r], 1);
        oc[p] = col[e];
        ov[p] = val[e];
    }
}

// ------------------------------ GEMM ----------------------------------------
// C[M,Nc] = A[M,K] @ B[K,Nc], row-major, fp32. BM=64, BN=128, BK=16, TM=4, TN=8.
// 256 threads. K % 16 == 0, Nc % 128 == 0 (holds: K in {512,128}, Nc in {128,512}).
#define BM 64
#define BN 128
#define BKK 16
#define TM 4
#define TN 8

__global__ __launch_bounds__(256) void k_gemm(const float* __restrict__ A,
                                              const float* __restrict__ B,
                                              float* __restrict__ C,
                                              int M, int Nc, int K) {
    __shared__ float As[BM][BKK + 1];
    __shared__ float Bs[BKK][BN];

    const int tx = threadIdx.x & 15;   // 0..15 -> 16*TN = 128 cols
    const int ty = threadIdx.x >> 4;   // 0..15 -> 16*TM = 64 rows
    const int rowBase = blockIdx.x * BM;
    const int colBase = blockIdx.y * BN;

    // A tile load mapping: thread -> (row 0..63, float4 col 0..3)
    const int ar  = threadIdx.x >> 2;
    const int ac4 = threadIdx.x & 3;
    // B tile load mapping: thread -> (k 0..7 (+8), float4 col 0..31)
    const int bk  = threadIdx.x >> 5;
    const int bc4 = threadIdx.x & 31;

    float acc[TM][TN];
    #pragma unroll
    for (int i = 0; i < TM; i++)
        #pragma unroll
        for (int j = 0; j < TN; j++) acc[i][j] = 0.f;

    for (int k0 = 0; k0 < K; k0 += BKK) {
        float4 av = make_float4(0.f, 0.f, 0.f, 0.f);
        int arow = rowBase + ar;
        if (arow < M)
            av = *(const float4*)(A + (size_t)arow * K + k0 + ac4 * 4);
        As[ar][ac4 * 4 + 0] = av.x;
        As[ar][ac4 * 4 + 1] = av.y;
        As[ar][ac4 * 4 + 2] = av.z;
        As[ar][ac4 * 4 + 3] = av.w;

        #pragma unroll
        for (int r = 0; r < 2; r++) {
            int kk = bk + r * 8;
            float4 bv = *(const float4*)(B + (size_t)(k0 + kk) * Nc + colBase + bc4 * 4);
            *(float4*)&Bs[kk][bc4 * 4] = bv;
        }
        __syncthreads();

        #pragma unroll
        for (int k = 0; k < BKK; k++) {
            float ra[TM], rb[TN];
            #pragma unroll
            for (int i = 0; i < TM; i++) ra[i] = As[ty * TM + i][k];
            #pragma unroll
            for (int j = 0; j < TN; j++) rb[j] = Bs[k][tx * TN + j];
            #pragma unroll
            for (int i = 0; i < TM; i++)
                #pragma unroll
                for (int j = 0; j < TN; j++)
                    acc[i][j] = fmaf(ra[i], rb[j], acc[i][j]);
        }
        __syncthreads();
    }

    #pragma unroll
    for (int i = 0; i < TM; i++) {
        int row = rowBase + ty * TM + i;
        if (row >= M) continue;
        #pragma unroll
        for (int j4 = 0; j4 < TN / 4; j4++) {
            float4 v = make_float4(acc[i][j4 * 4 + 0], acc[i][j4 * 4 + 1],
                                   acc[i][j4 * 4 + 2], acc[i][j4 * 4 + 3]);
            *(float4*)(C + (size_t)row * Nc + colBase + tx * TN + j4 * 4) = v;
        }
    }
}

// ------------------------------ SPMM ----------------------------------------
// out[row,:] = relu( sum_e val[e] * dense[col[e],:] + bias ), D=128: warp/row
__global__ __launch_bounds__(256) void k_spmm_relu_d128(
    const int* __restrict__ rs, const int* __restrict__ cols,
    const float* __restrict__ vals, const float* __restrict__ dense,
    const float* __restrict__ bias, float* __restrict__ out) {
    int warp = (blockIdx.x * blockDim.x + threadIdx.x) >> 5;
    int lane = threadIdx.x & 31;
    if (warp >= NROWS) return;
    int s = rs[warp], e = rs[warp + 1];
    float4 acc = make_float4(0.f, 0.f, 0.f, 0.f);
    for (int i = s; i < e; i++) {
        int   c = cols[i];
        float v = vals[i];
        float4 d = ((const float4*)(dense + (size_t)c * HID))[lane];
        acc.x = fmaf(v, d.x, acc.x);
        acc.y = fmaf(v, d.y, acc.y);
        acc.z = fmaf(v, d.z, acc.z);
        acc.w = fmaf(v, d.w, acc.w);
    }
    float4 b = ((const float4*)bias)[lane];
    acc.x = fmaxf(acc.x + b.x, 0.f);
    acc.y = fmaxf(acc.y + b.y, 0.f);
    acc.z = fmaxf(acc.z + b.z, 0.f);
    acc.w = fmaxf(acc.w + b.w, 0.f);
    ((float4*)(out + (size_t)warp * HID))[lane] = acc;
}

// D=512: one 128-thread block per row, one float4 per thread
__global__ __launch_bounds__(128) void k_spmm_relu_d512(
    const int* __restrict__ rs, const int* __restrict__ cols,
    const float* __restrict__ vals, const float* __restrict__ dense,
    const float* __restrict__ bias, float* __restrict__ out) {
    int row = blockIdx.x;
    int tid = threadIdx.x;
    int s = rs[row], e = rs[row + 1];
    float4 acc = make_float4(0.f, 0.f, 0.f, 0.f);
    for (int i = s; i < e; i++) {
        int   c = cols[i];
        float v = vals[i];
        float4 d = ((const float4*)(dense + (size_t)c * NFEAT))[tid];
        acc.x = fmaf(v, d.x, acc.x);
        acc.y = fmaf(v, d.y, acc.y);
        acc.z = fmaf(v, d.z, acc.z);
        acc.w = fmaf(v, d.w, acc.w);
    }
    float4 b = ((const float4*)bias)[tid];
    acc.x = fmaxf(acc.x + b.x, 0.f);
    acc.y = fmaxf(acc.y + b.y, 0.f);
    acc.z = fmaxf(acc.z + b.z, 0.f);
    acc.w = fmaxf(acc.w + b.w, 0.f);
    ((float4*)(out + (size_t)row * NFEAT))[tid] = acc;
}

// ------------------------------ launch --------------------------------------
extern "C" void kernel_launch(void* const* d_in, const int* in_sizes, int n_in,
                              void* d_out, int out_size) {
    const float* x           = (const float*)d_in[0];
    const int*   adj_row     = (const int*)d_in[1];
    const int*   adj_col     = (const int*)d_in[2];
    const float* adj_val     = (const float*)d_in[3];
    const int*   adj_inv_row = (const int*)d_in[4];
    const int*   adj_inv_col = (const int*)d_in[5];
    const float* adj_inv_val = (const float*)d_in[6];
    const float* W1          = (const float*)d_in[7];
    const float* b1          = (const float*)d_in[8];
    const float* W2          = (const float*)d_in[9];
    const float* b2          = (const float*)d_in[10];

    float* out = (float*)d_out;                           // [N, NFEAT]
    float* h   = out + (size_t)NROWS * NFEAT;             // [N, HID] embedding

    // resolve device-global scratch addresses
    float *xw, *hw, *val1, *val2;
    int *col1, *rs1, *col2, *rs2, *cnt, *next;
    cudaGetSymbolAddress((void**)&xw,   g_xw);
    cudaGetSymbolAddress((void**)&hw,   g_hw);
    cudaGetSymbolAddress((void**)&col1, g_col1);
    cudaGetSymbolAddress((void**)&val1, g_val1);
    cudaGetSymbolAddress((void**)&rs1,  g_rs1);
    cudaGetSymbolAddress((void**)&col2, g_col2);
    cudaGetSymbolAddress((void**)&val2, g_val2);
    cudaGetSymbolAddress((void**)&rs2,  g_rs2);
    cudaGetSymbolAddress((void**)&cnt,  g_cnt);
    cudaGetSymbolAddress((void**)&next, g_next);

    const int TB = 256;
    const int gN = (NROWS + TB - 1) / TB;
    const int gE = (NEDGE + TB - 1) / TB;

    // --- CSR build: graph 1 ---
    k_zero_int<<<gN, TB>>>(cnt, NROWS);
    k_hist<<<gE, TB>>>(adj_row, cnt);
    k_scan<<<1, 1024>>>(cnt, rs1, NROWS);
    k_copy_int<<<gN, TB>>>(rs1, next, NROWS);
    k_scatter<<<gE, TB>>>(adj_row, adj_col, adj_val, next, col1, val1);

    // --- CSR build: graph 2 ---
    k_zero_int<<<gN, TB>>>(cnt, NROWS);
    k_hist<<<gE, TB>>>(adj_inv_row, cnt);
    k_scan<<<1, 1024>>>(cnt, rs2, NROWS);
    k_copy_int<<<gN, TB>>>(rs2, next, NROWS);
    k_scatter<<<gE, TB>>>(adj_inv_row, adj_inv_col, adj_inv_val, next, col2, val2);

    // --- layer 1: xw = x @ W1 ; h = relu(A1 @ xw + b1) ---
    {
        dim3 grid((NROWS + BM - 1) / BM, HID / BN);
        k_gemm<<<grid, 256>>>(x, W1, xw, NROWS, HID, NFEAT);
    }
    k_spmm_relu_d128<<<(NROWS * 32 + TB - 1) / TB, TB>>>(rs1, col1, val1, xw, b1, h);

    // --- layer 2: hw = h @ W2 ; out = relu(A2 @ hw + b2) ---
    {
        dim3 grid((NROWS + BM - 1) / BM, NFEAT / BN);
        k_gemm<<<grid, 256>>>(h, W2, hw, NROWS, NFEAT, HID);
    }
    k_spmm_relu_d512<<<NROWS, 128>>>(rs2, col2, val2, hw, b2, out);
}

// round 2
// speedup vs baseline: 1.7221x; 1.7221x over previous
#include <cuda_runtime.h>
#include <cstdint>

#define NROWS 50000
#define NFEAT 512
#define HID   128
#define NEDGE 1600000

// ------------------------- scratch (device globals) -------------------------
__device__ float g_xw[(size_t)NROWS * HID];          // x@W1, then reused as A2@h
__device__ int   g_col1[NEDGE];
__device__ float g_val1[NEDGE];
__device__ int   g_rs1[NROWS + 1];
__device__ int   g_col2[NEDGE];
__device__ float g_val2[NEDGE];
__device__ int   g_rs2[NROWS + 1];
__device__ int   g_cnt[NROWS];
__device__ int   g_next[NROWS];

// ------------------------------ CSR build -----------------------------------
__global__ void k_zero_int(int* p, int n) {
    int i = blockIdx.x * blockDim.x + threadIdx.x;
    if (i < n) p[i] = 0;
}

__global__ void k_hist(const int* __restrict__ row, int* __restrict__ cnt) {
    int e = blockIdx.x * blockDim.x + threadIdx.x;
    if (e < NEDGE) atomicAdd(&cnt[row[e]], 1);
}

// single-block exclusive scan (warp-shuffle based); writes rs[0..n], rs[n]=total
__global__ __launch_bounds__(1024) void k_scan(const int* __restrict__ cnt,
                                               int* __restrict__ rs, int n) {
    __shared__ int wsum[32];
    __shared__ int carry;
    const int lane = threadIdx.x & 31;
    const int warp = threadIdx.x >> 5;
    if (threadIdx.x == 0) carry = 0;
    __syncthreads();
    for (int base = 0; base < n; base += 1024) {
        int i = base + (int)threadIdx.x;
        int v = (i < n) ? cnt[i] : 0;
        // inclusive warp scan
        int s = v;
        #pragma unroll
        for (int o = 1; o < 32; o <<= 1) {
            int t = __shfl_up_sync(0xffffffffu, s, o);
            if (lane >= o) s += t;
        }
        if (lane == 31) wsum[warp] = s;
        __syncthreads();
        if (warp == 0) {
            int ws = wsum[lane];
            #pragma unroll
            for (int o = 1; o < 32; o <<= 1) {
                int t = __shfl_up_sync(0xffffffffu, ws, o);
                if (lane >= o) ws += t;
            }
            wsum[lane] = ws;
        }
        __syncthreads();
        int excl = carry + (warp ? wsum[warp - 1] : 0) + s - v;
        if (i < n) rs[i] = excl;
        __syncthreads();                      // everyone has read carry
        if (threadIdx.x == 0) carry += wsum[31];
        __syncthreads();
    }
    if (threadIdx.x == 0) rs[n] = carry;
}

__global__ void k_copy_int(const int* __restrict__ a, int* __restrict__ b, int n) {
    int i = blockIdx.x * blockDim.x + threadIdx.x;
    if (i < n) b[i] = a[i];
}

__global__ void k_scatter(const int* __restrict__ row, const int* __restrict__ col,
                          const float* __restrict__ val, int* __restrict__ next,
                          int* __restrict__ oc, float* __restrict__ ov) {
    int e = blockIdx.x * blockDim.x + threadIdx.x;
    if (e < NEDGE) {
        int r = row[e];
        int p = atomicAdd(&next[r], 1);
        oc[p] = col[e];
        ov[p] = val[e];
    }
}

// ------------------------------ GEMM ----------------------------------------
// C[M,Nc] = A[M,K] @ B[K,Nc], fp32, 128x128x8 tile, 8x8 micro-tile, 256 thr.
// Requires K%8==0, Nc%128==0. If EPI: C = relu(C + bias).
#define GBM 128
#define GBN 128
#define GBK 8

template <bool EPI>
__global__ __launch_bounds__(256) void k_gemm128(const float* __restrict__ A,
                                                 const float* __restrict__ B,
                                                 float* __restrict__ C,
                                                 int M, int Nc, int K,
                                                 const float* __restrict__ bias) {
    __shared__ float As[GBK][GBM];
    __shared__ float Bs[GBK][GBN];

    const int tid = threadIdx.x;
    const int tx = tid & 15;     // 16 col groups
    const int ty = tid >> 4;     // 16 row groups
    const int rowBase = blockIdx.x * GBM;
    const int colBase = blockIdx.y * GBN;

    // A tile: 128 rows x 8 k. thread -> (row 0..127, k4 in {0,4})
    const int aRow = tid >> 1;
    const int aK4  = (tid & 1) * 4;
    // B tile: 8 k x 128 cols. thread -> (k 0..7, col4)
    const int bK  = tid >> 5;
    const int bC4 = (tid & 31) * 4;

    float acc[8][8];
    #pragma unroll
    for (int i = 0; i < 8; i++)
        #pragma unroll
        for (int j = 0; j < 8; j++) acc[i][j] = 0.f;

    for (int k0 = 0; k0 < K; k0 += GBK) {
        float4 av = make_float4(0.f, 0.f, 0.f, 0.f);
        if (rowBase + aRow < M)
            av = *(const float4*)(A + (size_t)(rowBase + aRow) * K + k0 + aK4);
        As[aK4 + 0][aRow] = av.x;
        As[aK4 + 1][aRow] = av.y;
        As[aK4 + 2][aRow] = av.z;
        As[aK4 + 3][aRow] = av.w;

        *(float4*)&Bs[bK][bC4] =
            *(const float4*)(B + (size_t)(k0 + bK) * Nc + colBase + bC4);
        __syncthreads();

        #pragma unroll
        for (int k = 0; k < GBK; k++) {
            float4 a0 = *(const float4*)&As[k][ty * 4];
            float4 a1 = *(const float4*)&As[k][ty * 4 + 64];
            float4 b0 = *(const float4*)&Bs[k][tx * 4];
            float4 b1 = *(const float4*)&Bs[k][tx * 4 + 64];
            float ra[8] = {a0.x, a0.y, a0.z, a0.w, a1.x, a1.y, a1.z, a1.w};
            float rb[8] = {b0.x, b0.y, b0.z, b0.w, b1.x, b1.y, b1.z, b1.w};
            #pragma unroll
            for (int i = 0; i < 8; i++)
                #pragma unroll
                for (int j = 0; j < 8; j++)
                    acc[i][j] = fmaf(ra[i], rb[j], acc[i][j]);
        }
        __syncthreads();
    }

    // bias (two float4 per thread, column-indexed)
    float4 bia0 = make_float4(0.f, 0.f, 0.f, 0.f), bia1 = bia0;
    if (EPI) {
        bia0 = *(const float4*)(bias + colBase + tx * 4);
        bia1 = *(const float4*)(bias + colBase + tx * 4 + 64);
    }

    #pragma unroll
    for (int i = 0; i < 8; i++) {
        int row = rowBase + ty * 4 + (i & 3) + (i >> 2) * 64;
        if (row >= M) continue;
        #pragma unroll
        for (int jg = 0; jg < 2; jg++) {
            float4 v = make_float4(acc[i][jg * 4 + 0], acc[i][jg * 4 + 1],
                                   acc[i][jg * 4 + 2], acc[i][jg * 4 + 3]);
            if (EPI) {
                float4 bb = jg ? bia1 : bia0;
                v.x = fmaxf(v.x + bb.x, 0.f);
                v.y = fmaxf(v.y + bb.y, 0.f);
                v.z = fmaxf(v.z + bb.z, 0.f);
                v.w = fmaxf(v.w + bb.w, 0.f);
            }
            *(float4*)(C + (size_t)row * Nc + colBase + tx * 4 + jg * 64) = v;
        }
    }
}

// ------------------------------ SPMM (D=128) --------------------------------
// out[row,:] = (relu(sum + bias)) or (sum), warp per row, float4 per lane
template <bool EPI>
__global__ __launch_bounds__(256) void k_spmm_d128(
    const int* __restrict__ rs, const int* __restrict__ cols,
    const float* __restrict__ vals, const float* __restrict__ dense,
    const float* __restrict__ bias, float* __restrict__ out) {
    int warp = (blockIdx.x * blockDim.x + threadIdx.x) >> 5;
    int lane = threadIdx.x & 31;
    if (warp >= NROWS) return;
    int s = rs[warp], e = rs[warp + 1];
    float4 acc = make_float4(0.f, 0.f, 0.f, 0.f);
    for (int i = s; i < e; i++) {
        int   c = __ldg(&cols[i]);
        float v = __ldg(&vals[i]);
        float4 d = ((const float4*)(dense + (size_t)c * HID))[lane];
        acc.x = fmaf(v, d.x, acc.x);
        acc.y = fmaf(v, d.y, acc.y);
        acc.z = fmaf(v, d.z, acc.z);
        acc.w = fmaf(v, d.w, acc.w);
    }
    if (EPI) {
        float4 b = ((const float4*)bias)[lane];
        acc.x = fmaxf(acc.x + b.x, 0.f);
        acc.y = fmaxf(acc.y + b.y, 0.f);
        acc.z = fmaxf(acc.z + b.z, 0.f);
        acc.w = fmaxf(acc.w + b.w, 0.f);
    }
    ((float4*)(out + (size_t)warp * HID))[lane] = acc;
}

// ------------------------------ launch --------------------------------------
extern "C" void kernel_launch(void* const* d_in, const int* in_sizes, int n_in,
                              void* d_out, int out_size) {
    const float* x           = (const float*)d_in[0];
    const int*   adj_row     = (const int*)d_in[1];
    const int*   adj_col     = (const int*)d_in[2];
    const float* adj_val     = (const float*)d_in[3];
    const int*   adj_inv_row = (const int*)d_in[4];
    const int*   adj_inv_col = (const int*)d_in[5];
    const float* adj_inv_val = (const float*)d_in[6];
    const float* W1          = (const float*)d_in[7];
    const float* b1          = (const float*)d_in[8];
    const float* W2          = (const float*)d_in[9];
    const float* b2          = (const float*)d_in[10];

    float* out = (float*)d_out;                           // [N, NFEAT]
    float* h   = out + (size_t)NROWS * NFEAT;             // [N, HID] embedding

    float *xw, *val1, *val2;
    int *col1, *rs1, *col2, *rs2, *cnt, *next;
    cudaGetSymbolAddress((void**)&xw,   g_xw);
    cudaGetSymbolAddress((void**)&col1, g_col1);
    cudaGetSymbolAddress((void**)&val1, g_val1);
    cudaGetSymbolAddress((void**)&rs1,  g_rs1);
    cudaGetSymbolAddress((void**)&col2, g_col2);
    cudaGetSymbolAddress((void**)&val2, g_val2);
    cudaGetSymbolAddress((void**)&rs2,  g_rs2);
    cudaGetSymbolAddress((void**)&cnt,  g_cnt);
    cudaGetSymbolAddress((void**)&next, g_next);

    const int TB = 256;
    const int gN = (NROWS + TB - 1) / TB;
    const int gE = (NEDGE + TB - 1) / TB;

    // --- CSR build: graph 1 (forward adjacency) ---
    k_zero_int<<<gN, TB>>>(cnt, NROWS);
    k_hist<<<gE, TB>>>(adj_row, cnt);
    k_scan<<<1, 1024>>>(cnt, rs1, NROWS);
    k_copy_int<<<gN, TB>>>(rs1, next, NROWS);
    k_scatter<<<gE, TB>>>(adj_row, adj_col, adj_val, next, col1, val1);

    // --- CSR build: graph 2 (inverse adjacency) ---
    k_zero_int<<<gN, TB>>>(cnt, NROWS);
    k_hist<<<gE, TB>>>(adj_inv_row, cnt);
    k_scan<<<1, 1024>>>(cnt, rs2, NROWS);
    k_copy_int<<<gN, TB>>>(rs2, next, NROWS);
    k_scatter<<<gE, TB>>>(adj_inv_row, adj_inv_col, adj_inv_val, next, col2, val2);

    // --- layer 1: xw = x @ W1 ; h = relu(A1 @ xw + b1) ---
    {
        dim3 grid((NROWS + GBM - 1) / GBM, HID / GBN);
        k_gemm128<false><<<grid, 256>>>(x, W1, xw, NROWS, HID, NFEAT, nullptr);
    }
    k_spmm_d128<true><<<(NROWS * 32 + TB - 1) / TB, TB>>>(rs1, col1, val1, xw, b1, h);

    // --- layer 2 (re-associated): g = A2 @ h ; out = relu(g @ W2 + b2) ---
    // A2 @ (h @ W2) == (A2 @ h) @ W2 — SPMM at D=128 instead of D=512
    k_spmm_d128<false><<<(NROWS * 32 + TB - 1) / TB, TB>>>(rs2, col2, val2, h, nullptr, xw);
    {
        dim3 grid((NROWS + GBM - 1) / GBM, NFEAT / GBN);
        k_gemm128<true><<<grid, 256>>>(xw, W2, out, NROWS, NFEAT, HID, b2);
    }
}

// round 4
// speedup vs baseline: 2.3224x; 1.3486x over previous
#include <cuda_runtime.h>
#include <cuda_bf16.h>
#include <cstdint>

#define NROWS 50000
#define MPAD  50048            // 391 * 128
#define NFEAT 512
#define HID   128
#define NEDGE 1600000

// ------------------------- scratch (device globals) -------------------------
__device__ float g_xw[(size_t)MPAD * HID];
__device__ __nv_bfloat16 g_abig[(size_t)MPAD * (3 * NFEAT)];   // A' [MPAD, 3K]
__device__ __nv_bfloat16 g_bbig[(size_t)NFEAT * (3 * NFEAT)];  // B' [N, 3K] (oversized)
__device__ int   g_col1[NEDGE];
__device__ float g_val1[NEDGE];
__device__ int   g_rs1[NROWS + 1];
__device__ int   g_col2[NEDGE];
__device__ float g_val2[NEDGE];
__device__ int   g_rs2[NROWS + 1];
__device__ int   g_cnt[NROWS];
__device__ int   g_next[NROWS];

// ------------------------------ CSR build -----------------------------------
__global__ void k_zero_int(int* p, int n) {
    int i = blockIdx.x * blockDim.x + threadIdx.x;
    if (i < n) p[i] = 0;
}
__global__ void k_hist(const int* __restrict__ row, int* __restrict__ cnt) {
    int e = blockIdx.x * blockDim.x + threadIdx.x;
    if (e < NEDGE) atomicAdd(&cnt[row[e]], 1);
}
__global__ __launch_bounds__(1024) void k_scan(const int* __restrict__ cnt,
                                               int* __restrict__ rs, int n) {
    __shared__ int wsum[32];
    __shared__ int carry;
    const int lane = threadIdx.x & 31;
    const int warp = threadIdx.x >> 5;
    if (threadIdx.x == 0) carry = 0;
    __syncthreads();
    for (int base = 0; base < n; base += 1024) {
        int i = base + (int)threadIdx.x;
        int v = (i < n) ? cnt[i] : 0;
        int s = v;
        #pragma unroll
        for (int o = 1; o < 32; o <<= 1) {
            int t = __shfl_up_sync(0xffffffffu, s, o);
            if (lane >= o) s += t;
        }
        if (lane == 31) wsum[warp] = s;
        __syncthreads();
        if (warp == 0) {
            int ws = wsum[lane];
            #pragma unroll
            for (int o = 1; o < 32; o <<= 1) {
                int t = __shfl_up_sync(0xffffffffu, ws, o);
                if (lane >= o) ws += t;
            }
            wsum[lane] = ws;
        }
        __syncthreads();
        int excl = carry + (warp ? wsum[warp - 1] : 0) + s - v;
        if (i < n) rs[i] = excl;
        __syncthreads();
        if (threadIdx.x == 0) carry += wsum[31];
        __syncthreads();
    }
    if (threadIdx.x == 0) rs[n] = carry;
}
__global__ void k_copy_int(const int* __restrict__ a, int* __restrict__ b, int n) {
    int i = blockIdx.x * blockDim.x + threadIdx.x;
    if (i < n) b[i] = a[i];
}
__global__ void k_scatter(const int* __restrict__ row, const int* __restrict__ col,
                          const float* __restrict__ val, int* __restrict__ next,
                          int* __restrict__ oc, float* __restrict__ ov) {
    int e = blockIdx.x * blockDim.x + threadIdx.x;
    if (e < NEDGE) {
        int r = row[e];
        int p = atomicAdd(&next[r], 1);
        oc[p] = col[e];
        ov[p] = val[e];
    }
}

// --------------------- fp32 -> bf16 split (K-concatenated) -------------------
// A [rows<=NROWS, K] fp32 -> A' [MPAD, 3K] bf16 laid out [hi | lo | hi]
__global__ void k_split3(const float* __restrict__ in, __nv_bfloat16* __restrict__ outp,
                         int K, int validRows) {
    long t = ((long)blockIdx.x * blockDim.x + threadIdx.x) * 4;
    if (t >= (long)MPAD * K) return;
    int row = (int)(t / K);
    int k   = (int)(t % K);
    float4 a = make_float4(0.f, 0.f, 0.f, 0.f);
    if (row < validRows) a = *(const float4*)(in + (size_t)row * K + k);
    __nv_bfloat16 h0 = __float2bfloat16(a.x), h1 = __float2bfloat16(a.y);
    __nv_bfloat16 h2 = __float2bfloat16(a.z), h3 = __float2bfloat16(a.w);
    __nv_bfloat162 hA(h0, h1), hB(h2, h3);
    __nv_bfloat162 lA(__float2bfloat16(a.x - __bfloat162float(h0)),
                      __float2bfloat16(a.y - __bfloat162float(h1)));
    __nv_bfloat162 lB(__float2bfloat16(a.z - __bfloat162float(h2)),
                      __float2bfloat16(a.w - __bfloat162float(h3)));
    size_t base = (size_t)row * (3 * K) + k;
    *(__nv_bfloat162*)(outp + base)             = hA;
    *(__nv_bfloat162*)(outp + base + 2)         = hB;
    *(__nv_bfloat162*)(outp + base + K)         = lA;
    *(__nv_bfloat162*)(outp + base + K + 2)     = lB;
    *(__nv_bfloat162*)(outp + base + 2 * K)     = hA;
    *(__nv_bfloat162*)(outp + base + 2 * K + 2) = hB;
}

// W [K, N] fp32 -> B' [N, 3K] bf16 laid out [hi | hi | lo] (transposed)
__global__ void k_splitw3(const float* __restrict__ W, __nv_bfloat16* __restrict__ outp,
                          int K, int N) {
    int i = blockIdx.x * blockDim.x + threadIdx.x;
    if (i >= K * N) return;
    int k = i / N, n = i % N;
    float a = W[i];
    __nv_bfloat16 h = __float2bfloat16(a);
    __nv_bfloat16 l = __float2bfloat16(a - __bfloat162float(h));
    size_t base = (size_t)n * (3 * K);
    outp[base + k]         = h;
    outp[base + K + k]     = h;
    outp[base + 2 * K + k] = l;
}

// --------------------------- mma.sync bf16 GEMM ------------------------------
// C[M,Nc] fp32 = A'[MPAD,Kp] bf16 @ B'[Nc,Kp]^T. CTA 128x128, BK=64, 8 warps.
// Warp tile 64x32 via m16n8k16. cp.async double-buffered. If EPI: relu(C+bias).
#define SROW 144                      // smem row stride bytes (64 bf16 + 8 pad)
#define ABYTES (128 * SROW)           // 18432
#define GSMEM (4 * ABYTES)            // A0,A1,B0,B1 = 73728

__device__ __forceinline__ uint32_t smem_u32(const void* p) {
    uint32_t a;
    asm("{ .reg .u64 t; cvta.to.shared.u64 t, %1; cvt.u32.u64 %0, t; }" : "=r"(a) : "l"(p));
    return a;
}
__device__ __forceinline__ void cpa16(uint32_t s, const void* g) {
    asm volatile("cp.async.cg.shared.global [%0], [%1], 16;" :: "r"(s), "l"(g));
}
__device__ __forceinline__ void ldm_x4(uint32_t* r, uint32_t a) {
    asm volatile("ldmatrix.sync.aligned.m8n8.x4.shared.b16 {%0,%1,%2,%3}, [%4];"
                 : "=r"(r[0]), "=r"(r[1]), "=r"(r[2]), "=r"(r[3]) : "r"(a));
}
__device__ __forceinline__ void ldm_x2(uint32_t* r, uint32_t a) {
    asm volatile("ldmatrix.sync.aligned.m8n8.x2.shared.b16 {%0,%1}, [%2];"
                 : "=r"(r[0]), "=r"(r[1]) : "r"(a));
}
__device__ __forceinline__ void mma16816(float* d, const uint32_t* a, const uint32_t* b) {
    asm volatile("mma.sync.aligned.m16n8k16.row.col.f32.bf16.bf16.f32 "
                 "{%0,%1,%2,%3}, {%4,%5,%6,%7}, {%8,%9}, {%0,%1,%2,%3};"
                 : "+f"(d[0]), "+f"(d[1]), "+f"(d[2]), "+f"(d[3])
                 : "r"(a[0]), "r"(a[1]), "r"(a[2]), "r"(a[3]), "r"(b[0]), "r"(b[1]));
}

template <bool EPI>
__global__ __launch_bounds__(256) void k_gemm_mma(
    const __nv_bfloat16* __restrict__ Ap, const __nv_bfloat16* __restrict__ Bp,
    float* __restrict__ C, int M, int Nc, int Kp, const float* __restrict__ bias) {
    extern __shared__ char sm[];
    char* bufA[2] = {sm, sm + ABYTES};
    char* bufB[2] = {sm + 2 * ABYTES, sm + 3 * ABYTES};

    const int tid  = threadIdx.x;
    const int lane = tid & 31;
    const int wid  = tid >> 5;
    const int warpM = wid & 1;        // 2 warps in M
    const int warpN = wid >> 1;       // 4 warps in N
    const int rowBase = blockIdx.x * 128;
    const int colBase = blockIdx.y * 128;

    // global load mapping: 8 threads/row (16B each), 32 rows/pass, 4 passes
    const int gr  = tid >> 3;         // 0..31
    const int gc  = (tid & 7) * 16;   // byte offset in 128B row-chunk
    const size_t kb2 = (size_t)Kp * 2;
    const char* gA = (const char*)Ap + (size_t)rowBase * kb2 + gc;
    const char* gB = (const char*)Bp + (size_t)colBase * kb2 + gc;
    uint32_t sA[2], sB[2];
    sA[0] = smem_u32(bufA[0]); sA[1] = smem_u32(bufA[1]);
    sB[0] = smem_u32(bufB[0]); sB[1] = smem_u32(bufB[1]);
    const uint32_t sOff = gr * SROW + gc;

    const int nIter = Kp / 64;

    // prefetch tile 0
    {
        const size_t ko = 0;
        #pragma unroll
        for (int p = 0; p < 4; p++) {
            int r = gr + p * 32;
            cpa16(sA[0] + sOff + p * 32 * SROW, gA + (size_t)r * kb2 + ko);
            cpa16(sB[0] + sOff + p * 32 * SROW, gB + (size_t)r * kb2 + ko);
        }
        asm volatile("cp.async.commit_group;");
    }

    // ldmatrix lane addressing
    const int aRow = (lane & 7) + ((lane >> 3) & 1) * 8;   // 0..15
    const int aK   = ((lane >> 4) & 1) * 8;                // 0/8
    const int bRow = lane & 7;
    const int bK   = ((lane >> 3) & 1) * 8;
    const uint32_t aBase = (warpM * 64 + aRow) * SROW + aK * 2;
    const uint32_t bBase = (warpN * 32 + bRow) * SROW + bK * 2;

    float acc[4][4][4];
    #pragma unroll
    for (int i = 0; i < 4; i++)
        #pragma unroll
        for (int j = 0; j < 4; j++)
            #pragma unroll
            for (int q = 0; q < 4; q++) acc[i][j][q] = 0.f;

    for (int it = 0; it < nIter; it++) {
        asm volatile("cp.async.wait_group 0;");
        __syncthreads();
        const int cur = it & 1;
        if (it + 1 < nIter) {
            const int nxt = cur ^ 1;
            const size_t ko = (size_t)(it + 1) * 128;   // 64 bf16 = 128 bytes
            #pragma unroll
            for (int p = 0; p < 4; p++) {
                int r = gr + p * 32;
                cpa16(sA[nxt] + sOff + p * 32 * SROW, gA + (size_t)r * kb2 + ko);
                cpa16(sB[nxt] + sOff + p * 32 * SROW, gB + (size_t)r * kb2 + ko);
            }
            asm volatile("cp.async.commit_group;");
        }
        const uint32_t a0 = sA[cur] + aBase;
        const uint32_t b0 = sB[cur] + bBase;
        #pragma unroll
        for (int kb = 0; kb < 4; kb++) {
            uint32_t af[4][4], bf[4][2];
            #pragma unroll
            for (int i = 0; i < 4; i++)
                ldm_x4(af[i], a0 + i * 16 * SROW + kb * 32);
            #pragma unroll
            for (int j = 0; j < 4; j++)
                ldm_x2(bf[j], b0 + j * 8 * SROW + kb * 32);
            #pragma unroll
            for (int i = 0; i < 4; i++)
                #pragma unroll
                for (int j = 0; j < 4; j++)
                    mma16816(acc[i][j], af[i], bf[j]);
        }
    }

    // epilogue
    #pragma unroll
    for (int i = 0; i < 4; i++) {
        int r0 = rowBase + warpM * 64 + i * 16 + (lane >> 2);
        #pragma unroll
        for (int j = 0; j < 4; j++) {
            int c0 = colBase + warpN * 32 + j * 8 + (lane & 3) * 2;
            float2 v0 = make_float2(acc[i][j][0], acc[i][j][1]);
            float2 v1 = make_float2(acc[i][j][2], acc[i][j][3]);
            if (EPI) {
                float2 b = *(const float2*)(bias + c0);
                v0.x = fmaxf(v0.x + b.x, 0.f); v0.y = fmaxf(v0.y + b.y, 0.f);
                v1.x = fmaxf(v1.x + b.x, 0.f); v1.y = fmaxf(v1.y + b.y, 0.f);
            }
            if (r0 < M)     *(float2*)(C + (size_t)r0 * Nc + c0)       = v0;
            if (r0 + 8 < M) *(float2*)(C + (size_t)(r0 + 8) * Nc + c0) = v1;
        }
    }
}

// ------------------------------ SPMM (D=128) --------------------------------
template <bool EPI>
__global__ __launch_bounds__(256) void k_spmm_d128(
    const int* __restrict__ rs, const int* __restrict__ cols,
    const float* __restrict__ vals, const float* __restrict__ dense,
    const float* __restrict__ bias, float* __restrict__ out) {
    int warp = (blockIdx.x * blockDim.x + threadIdx.x) >> 5;
    int lane = threadIdx.x & 31;
    if (warp >= NROWS) return;
    int s = rs[warp], e = rs[warp + 1];
    float4 acc = make_float4(0.f, 0.f, 0.f, 0.f);
    for (int i = s; i < e; i++) {
        int   c = __ldg(&cols[i]);
        float v = __ldg(&vals[i]);
        float4 d = ((const float4*)(dense + (size_t)c * HID))[lane];
        acc.x = fmaf(v, d.x, acc.x);
        acc.y = fmaf(v, d.y, acc.y);
        acc.z = fmaf(v, d.z, acc.z);
        acc.w = fmaf(v, d.w, acc.w);
    }
    if (EPI) {
        float4 b = ((const float4*)bias)[lane];
        acc.x = fmaxf(acc.x + b.x, 0.f);
        acc.y = fmaxf(acc.y + b.y, 0.f);
        acc.z = fmaxf(acc.z + b.z, 0.f);
        acc.w = fmaxf(acc.w + b.w, 0.f);
    }
    ((float4*)(out + (size_t)warp * HID))[lane] = acc;
}

// ------------------------------ launch --------------------------------------
extern "C" void kernel_launch(void* const* d_in, const int* in_sizes, int n_in,
                              void* d_out, int out_size) {
    const float* x           = (const float*)d_in[0];
    const int*   adj_row     = (const int*)d_in[1];
    const int*   adj_col     = (const int*)d_in[2];
    const float* adj_val     = (const float*)d_in[3];
    const int*   adj_inv_row = (const int*)d_in[4];
    const int*   adj_inv_col = (const int*)d_in[5];
    const float* adj_inv_val = (const float*)d_in[6];
    const float* W1          = (const float*)d_in[7];
    const float* b1          = (const float*)d_in[8];
    const float* W2          = (const float*)d_in[9];
    const float* b2          = (const float*)d_in[10];

    float* out = (float*)d_out;                   // [N, NFEAT]
    float* h   = out + (size_t)NROWS * NFEAT;     // [N, HID]

    float *xw, *val1, *val2;
    __nv_bfloat16 *abig, *bbig;
    int *col1, *rs1, *col2, *rs2, *cnt, *next;
    cudaGetSymbolAddress((void**)&xw,   g_xw);
    cudaGetSymbolAddress((void**)&abig, g_abig);
    cudaGetSymbolAddress((void**)&bbig, g_bbig);
    cudaGetSymbolAddress((void**)&col1, g_col1);
    cudaGetSymbolAddress((void**)&val1, g_val1);
    cudaGetSymbolAddress((void**)&rs1,  g_rs1);
    cudaGetSymbolAddress((void**)&col2, g_col2);
    cudaGetSymbolAddress((void**)&val2, g_val2);
    cudaGetSymbolAddress((void**)&rs2,  g_rs2);
    cudaGetSymbolAddress((void**)&cnt,  g_cnt);
    cudaGetSymbolAddress((void**)&next, g_next);

    cudaFuncSetAttribute(k_gemm_mma<false>,
                         cudaFuncAttributeMaxDynamicSharedMemorySize, GSMEM);
    cudaFuncSetAttribute(k_gemm_mma<true>,
                         cudaFuncAttributeMaxDynamicSharedMemorySize, GSMEM);

    const int TB = 256;
    const int gN = (NROWS + TB - 1) / TB;
    const int gE = (NEDGE + TB - 1) / TB;

    // --- CSR build: graph 1 ---
    k_zero_int<<<gN, TB>>>(cnt, NROWS);
    k_hist<<<gE, TB>>>(adj_row, cnt);
    k_scan<<<1, 1024>>>(cnt, rs1, NROWS);
    k_copy_int<<<gN, TB>>>(rs1, next, NROWS);
    k_scatter<<<gE, TB>>>(adj_row, adj_col, adj_val, next, col1, val1);

    // --- CSR build: graph 2 ---
    k_zero_int<<<gN, TB>>>(cnt, NROWS);
    k_hist<<<gE, TB>>>(adj_inv_row, cnt);
    k_scan<<<1, 1024>>>(cnt, rs2, NROWS);
    k_copy_int<<<gN, TB>>>(rs2, next, NROWS);
    k_scatter<<<gE, TB>>>(adj_inv_row, adj_inv_col, adj_inv_val, next, col2, val2);

    // --- layer 1: xw = x @ W1 (bf16-split mma, K'=1536) ---
    {
        long np = (long)MPAD * NFEAT;
        k_split3<<<(int)((np / 4 + TB - 1) / TB), TB>>>(x, abig, NFEAT, NROWS);
        k_splitw3<<<(NFEAT * HID + TB - 1) / TB, TB>>>(W1, bbig, NFEAT, HID);
        dim3 grid(MPAD / 128, HID / 128);
        k_gemm_mma<false><<<grid, 256, GSMEM>>>(abig, bbig, xw,
                                                NROWS, HID, 3 * NFEAT, nullptr);
    }
    // h = relu(A1 @ xw + b1)
    k_spmm_d128<true><<<(NROWS * 32 + TB - 1) / TB, TB>>>(rs1, col1, val1, xw, b1, h);

    // --- layer 2 (re-associated): g = A2 @ h ; out = relu(g @ W2 + b2) ---
    k_spmm_d128<false><<<(NROWS * 32 + TB - 1) / TB, TB>>>(rs2, col2, val2, h, nullptr, xw);
    {
        long np = (long)MPAD * HID;
        k_split3<<<(int)((np / 4 + TB - 1) / TB), TB>>>(xw, abig, HID, NROWS);
        k_splitw3<<<(HID * NFEAT + TB - 1) / TB, TB>>>(W2, bbig, HID, NFEAT);
        dim3 grid(MPAD / 128, NFEAT / 128);
        k_gemm_mma<true><<<grid, 256, GSMEM>>>(abig, bbig, out,
                                               NROWS, NFEAT, 3 * HID, b2);
    }
}

// round 5
// speedup vs baseline: 2.8442x; 1.2247x over previous
#include <cuda_runtime.h>
#include <cuda_bf16.h>
#include <cstdint>

#define NROWS 50000
#define MPAD  50048            // 391 * 128
#define NFEAT 512
#define HID   128
#define NEDGE 1600000

// ------------------------- scratch (device globals) -------------------------
__device__ float g_xw[(size_t)NROWS * HID];
__device__ __nv_bfloat16 g_bh1[HID * NFEAT];    // W1^T hi  [128, 512]
__device__ __nv_bfloat16 g_bl1[HID * NFEAT];
__device__ __nv_bfloat16 g_bh2[NFEAT * HID];    // W2^T hi  [512, 128]
__device__ __nv_bfloat16 g_bl2[NFEAT * HID];
__device__ int   g_col1[NEDGE];
__device__ float g_val1[NEDGE];
__device__ int   g_rs1[NROWS + 1];
__device__ int   g_col2[NEDGE];
__device__ float g_val2[NEDGE];
__device__ int   g_rs2[NROWS + 1];
__device__ int   g_cnt[2 * NROWS];
__device__ int   g_next[2 * NROWS];

// --------------------------- CSR build (fused) -------------------------------
__global__ void k_zero2(int* p) {
    int i = blockIdx.x * blockDim.x + threadIdx.x;
    if (i < 2 * NROWS) p[i] = 0;
}

__global__ void k_hist2(const int* __restrict__ r1, const int* __restrict__ r2,
                        int* __restrict__ cnt) {
    long i = (long)blockIdx.x * blockDim.x + threadIdx.x;
    if (i < NEDGE)               atomicAdd(&cnt[r1[i]], 1);
    else if (i < 2L * NEDGE)     atomicAdd(&cnt[NROWS + r2[i - NEDGE]], 1);
}

// 2 blocks; block g scans cnt[g*NROWS..] -> rs_g (and next copy)
__global__ __launch_bounds__(1024) void k_scan2(const int* __restrict__ cnt,
                                                int* __restrict__ rs1,
                                                int* __restrict__ rs2,
                                                int* __restrict__ next) {
    __shared__ int wsum[32];
    __shared__ int carry;
    const int g = blockIdx.x;
    const int* c = cnt + g * NROWS;
    int* rs = g ? rs2 : rs1;
    int* nx = next + g * NROWS;
    const int lane = threadIdx.x & 31;
    const int warp = threadIdx.x >> 5;
    if (threadIdx.x == 0) carry = 0;
    __syncthreads();
    for (int base = 0; base < NROWS; base += 1024) {
        int i = base + (int)threadIdx.x;
        int v = (i < NROWS) ? c[i] : 0;
        int s = v;
        #pragma unroll
        for (int o = 1; o < 32; o <<= 1) {
            int t = __shfl_up_sync(0xffffffffu, s, o);
            if (lane >= o) s += t;
        }
        if (lane == 31) wsum[warp] = s;
        __syncthreads();
        if (warp == 0) {
            int ws = wsum[lane];
            #pragma unroll
            for (int o = 1; o < 32; o <<= 1) {
                int t = __shfl_up_sync(0xffffffffu, ws, o);
                if (lane >= o) ws += t;
            }
            wsum[lane] = ws;
        }
        __syncthreads();
        int excl = carry + (warp ? wsum[warp - 1] : 0) + s - v;
        if (i < NROWS) { rs[i] = excl; nx[i] = excl; }
        __syncthreads();
        if (threadIdx.x == 0) carry += wsum[31];
        __syncthreads();
    }
    if (threadIdx.x == 0) rs[NROWS] = carry;
}

__global__ void k_scatter2(const int* __restrict__ r1, const int* __restrict__ c1,
                           const float* __restrict__ v1,
                           const int* __restrict__ r2, const int* __restrict__ c2,
                           const float* __restrict__ v2,
                           int* __restrict__ next,
                           int* __restrict__ oc1, float* __restrict__ ov1,
                           int* __restrict__ oc2, float* __restrict__ ov2) {
    long i = (long)blockIdx.x * blockDim.x + threadIdx.x;
    if (i < NEDGE) {
        int r = r1[i];
        int p = atomicAdd(&next[r], 1);
        oc1[p] = c1[i]; ov1[p] = v1[i];
    } else if (i < 2L * NEDGE) {
        long e = i - NEDGE;
        int r = r2[e];
        int p = atomicAdd(&next[NROWS + r], 1);
        oc2[p] = c2[e]; ov2[p] = v2[e];
    }
}

// --------------------- W split+transpose: W[K,N] -> Bh/Bl [N,K] --------------
__global__ void k_splitw2(const float* __restrict__ W, __nv_bfloat16* __restrict__ bh,
                          __nv_bfloat16* __restrict__ bl, int K, int N) {
    int i = blockIdx.x * blockDim.x + threadIdx.x;
    if (i >= K * N) return;
    int k = i / N, n = i % N;
    float a = W[i];
    __nv_bfloat16 h = __float2bfloat16(a);
    bh[(size_t)n * K + k] = h;
    bl[(size_t)n * K + k] = __float2bfloat16(a - __bfloat162float(h));
}

// ----------------- fused-split mma.sync bf16 GEMM -----------------------------
// C[M,Nc] fp32 = A[M,K] fp32 @ (Bh+Bl)[Nc,K]^T with in-kernel A hi/lo split.
// Computes Ahi*Bh + Ahi*Bl + Alo*Bh. CTA 128x128, BK=32, 8 warps (64x32 tiles).
#define BK 32
#define SROW2 80                      // 32 bf16 (64B) + 16B pad: conflict-free ldmatrix
#define TILE2 (128 * SROW2)           // 10240
#define GSMEM2 (8 * TILE2)            // 81920: AH0 AH1 AL0 AL1 BH0 BH1 BL0 BL1

__device__ __forceinline__ uint32_t smem_u32(const void* p) {
    uint32_t a;
    asm("{ .reg .u64 t; cvta.to.shared.u64 t, %1; cvt.u32.u64 %0, t; }" : "=r"(a) : "l"(p));
    return a;
}
__device__ __forceinline__ void cpa16(uint32_t s, const void* g) {
    asm volatile("cp.async.cg.shared.global [%0], [%1], 16;" :: "r"(s), "l"(g));
}
__device__ __forceinline__ void ldm_x4(uint32_t* r, uint32_t a) {
    asm volatile("ldmatrix.sync.aligned.m8n8.x4.shared.b16 {%0,%1,%2,%3}, [%4];"
                 : "=r"(r[0]), "=r"(r[1]), "=r"(r[2]), "=r"(r[3]) : "r"(a));
}
__device__ __forceinline__ void ldm_x2(uint32_t* r, uint32_t a) {
    asm volatile("ldmatrix.sync.aligned.m8n8.x2.shared.b16 {%0,%1}, [%2];"
                 : "=r"(r[0]), "=r"(r[1]) : "r"(a));
}
__device__ __forceinline__ void mma16816(float* d, const uint32_t* a, const uint32_t* b) {
    asm volatile("mma.sync.aligned.m16n8k16.row.col.f32.bf16.bf16.f32 "
                 "{%0,%1,%2,%3}, {%4,%5,%6,%7}, {%8,%9}, {%0,%1,%2,%3};"
                 : "+f"(d[0]), "+f"(d[1]), "+f"(d[2]), "+f"(d[3])
                 : "r"(a[0]), "r"(a[1]), "r"(a[2]), "r"(a[3]), "r"(b[0]), "r"(b[1]));
}
__device__ __forceinline__ uint32_t pack_bf2(float x, float y) {
    __nv_bfloat162 t(__float2bfloat16(x), __float2bfloat16(y));
    return *(uint32_t*)&t;
}

template <bool EPI>
__global__ void __launch_bounds__(256, 2) k_gemm_f(
    const float* __restrict__ A, const __nv_bfloat16* __restrict__ Bh,
    const __nv_bfloat16* __restrict__ Bl, float* __restrict__ C,
    int M, int Nc, int K, const float* __restrict__ bias) {
    extern __shared__ char sm[];
    const uint32_t s0 = smem_u32(sm);
    const uint32_t sAH0 = s0,              sAH1 = s0 + TILE2;
    const uint32_t sAL0 = s0 + 2 * TILE2,  sAL1 = s0 + 3 * TILE2;
    const uint32_t sBH0 = s0 + 4 * TILE2,  sBH1 = s0 + 5 * TILE2;
    const uint32_t sBL0 = s0 + 6 * TILE2,  sBL1 = s0 + 7 * TILE2;

    const int tid  = threadIdx.x;
    const int lane = tid & 31;
    const int wid  = tid >> 5;
    const int warpM = wid & 1;
    const int warpN = wid >> 1;
    const int rowBase = blockIdx.x * 128;
    const int colBase = blockIdx.y * 128;

    // A: 128 rows x 32 fp32. thread -> (row tid>>3 [+32*p], float4 col tid&7)
    const int ar  = tid >> 3;
    const int ac4 = tid & 7;
    // B: 128 rows x 32 bf16 (64B). thread -> row tid>>1, segs {b0, b0+32}
    const int br = tid >> 1;
    const int b0 = (tid & 1) * 16;
    const char* gBh = (const char*)(Bh + (size_t)(colBase + br) * K);
    const char* gBl = (const char*)(Bl + (size_t)(colBase + br) * K);
    const uint32_t bDst = br * SROW2 + b0;

    const int nIter = K / BK;

    float4 ra[4];
    #pragma unroll
    for (int p = 0; p < 4; p++) {
        int row = rowBase + ar + p * 32;
        ra[p] = (row < M) ? *(const float4*)(A + (size_t)row * K + ac4 * 4)
                          : make_float4(0.f, 0.f, 0.f, 0.f);
    }
    cpa16(sBH0 + bDst,      gBh + b0);
    cpa16(sBH0 + bDst + 32, gBh + b0 + 32);
    cpa16(sBL0 + bDst,      gBl + b0);
    cpa16(sBL0 + bDst + 32, gBl + b0 + 32);
    asm volatile("cp.async.commit_group;");

    // ldmatrix lane addressing (validated in R4)
    const int aRow = (lane & 7) + ((lane >> 3) & 1) * 8;
    const int aK   = ((lane >> 4) & 1) * 8;
    const int bRow = lane & 7;
    const int bK   = ((lane >> 3) & 1) * 8;
    const uint32_t aOff = (warpM * 64 + aRow) * SROW2 + aK * 2;
    const uint32_t bOff = (warpN * 32 + bRow) * SROW2 + bK * 2;

    float acc[4][4][4];
    #pragma unroll
    for (int i = 0; i < 4; i++)
        #pragma unroll
        for (int j = 0; j < 4; j++)
            #pragma unroll
            for (int q = 0; q < 4; q++) acc[i][j][q] = 0.f;

    for (int it = 0; it < nIter; it++) {
        const int cur = it & 1;
        const uint32_t aH = cur ? sAH1 : sAH0;
        const uint32_t aL = cur ? sAL1 : sAL0;
        const uint32_t bH = cur ? sBH1 : sBH0;
        const uint32_t bL = cur ? sBL1 : sBL0;

        // convert + store A hi/lo into current buffers
        #pragma unroll
        for (int p = 0; p < 4; p++) {
            float4 v = ra[p];
            uint32_t h01 = pack_bf2(v.x, v.y);
            uint32_t h23 = pack_bf2(v.z, v.w);
            float hx = __bfloat162float(__float2bfloat16(v.x));
            float hy = __bfloat162float(__float2bfloat16(v.y));
            float hz = __bfloat162float(__float2bfloat16(v.z));
            float hw = __bfloat162float(__float2bfloat16(v.w));
            uint32_t l01 = pack_bf2(v.x - hx, v.y - hy);
            uint32_t l23 = pack_bf2(v.z - hz, v.w - hw);
            uint32_t dst = (uint32_t)(ar + p * 32) * SROW2 + ac4 * 8;
            asm volatile("st.shared.v2.b32 [%0], {%1,%2};" :: "r"(aH + dst), "r"(h01), "r"(h23));
            asm volatile("st.shared.v2.b32 [%0], {%1,%2};" :: "r"(aL + dst), "r"(l01), "r"(l23));
        }

        if (it + 1 < nIter) {
            const uint32_t nBH = cur ? sBH0 : sBH1;
            const uint32_t nBL = cur ? sBL0 : sBL1;
            const size_t ko = (size_t)(it + 1) * 64;      // 32 bf16 = 64 bytes
            cpa16(nBH + bDst,      gBh + ko + b0);
            cpa16(nBH + bDst + 32, gBh + ko + b0 + 32);
            cpa16(nBL + bDst,      gBl + ko + b0);
            cpa16(nBL + bDst + 32, gBl + ko + b0 + 32);
            asm volatile("cp.async.commit_group;");
            const int kf = (it + 1) * 32 + ac4 * 4;
            #pragma unroll
            for (int p = 0; p < 4; p++) {
                int row = rowBase + ar + p * 32;
                ra[p] = (row < M) ? *(const float4*)(A + (size_t)row * K + kf)
                                  : make_float4(0.f, 0.f, 0.f, 0.f);
            }
            asm volatile("cp.async.wait_group 1;");
        } else {
            asm volatile("cp.async.wait_group 0;");
        }
        __syncthreads();

        #pragma unroll
        for (int kb = 0; kb < 2; kb++) {
            uint32_t bfH[4][2], bfL[4][2];
            #pragma unroll
            for (int j = 0; j < 4; j++) {
                ldm_x2(bfH[j], bH + bOff + j * 8 * SROW2 + kb * 32);
                ldm_x2(bfL[j], bL + bOff + j * 8 * SROW2 + kb * 32);
            }
            #pragma unroll
            for (int i = 0; i < 4; i++) {
                uint32_t afH[4], afL[4];
                ldm_x4(afH, aH + aOff + i * 16 * SROW2 + kb * 32);
                ldm_x4(afL, aL + aOff + i * 16 * SROW2 + kb * 32);
                #pragma unroll
                for (int j = 0; j < 4; j++) {
                    mma16816(acc[i][j], afH, bfH[j]);
                    mma16816(acc[i][j], afH, bfL[j]);
                    mma16816(acc[i][j], afL, bfH[j]);
                }
            }
        }
        __syncthreads();
    }

    // epilogue (layout validated in R4)
    #pragma unroll
    for (int i = 0; i < 4; i++) {
        int r0 = rowBase + warpM * 64 + i * 16 + (lane >> 2);
        #pragma unroll
        for (int j = 0; j < 4; j++) {
            int c0 = colBase + warpN * 32 + j * 8 + (lane & 3) * 2;
            float2 v0 = make_float2(acc[i][j][0], acc[i][j][1]);
            float2 v1 = make_float2(acc[i][j][2], acc[i][j][3]);
            if (EPI) {
                float2 b = *(const float2*)(bias + c0);
                v0.x = fmaxf(v0.x + b.x, 0.f); v0.y = fmaxf(v0.y + b.y, 0.f);
                v1.x = fmaxf(v1.x + b.x, 0.f); v1.y = fmaxf(v1.y + b.y, 0.f);
            }
            if (r0 < M)     *(float2*)(C + (size_t)r0 * Nc + c0)       = v0;
            if (r0 + 8 < M) *(float2*)(C + (size_t)(r0 + 8) * Nc + c0) = v1;
        }
    }
}

// ------------------------------ SPMM (D=128) --------------------------------
template <bool EPI>
__global__ __launch_bounds__(256) void k_spmm_d128(
    const int* __restrict__ rs, const int* __restrict__ cols,
    const float* __restrict__ vals, const float* __restrict__ dense,
    const float* __restrict__ bias, float* __restrict__ out) {
    int warp = (blockIdx.x * blockDim.x + threadIdx.x) >> 5;
    int lane = threadIdx.x & 31;
    if (warp >= NROWS) return;
    int s = rs[warp], e = rs[warp + 1];
    float4 acc = make_float4(0.f, 0.f, 0.f, 0.f);
    for (int i = s; i < e; i++) {
        int   c = __ldg(&cols[i]);
        float v = __ldg(&vals[i]);
        float4 d = ((const float4*)(dense + (size_t)c * HID))[lane];
        acc.x = fmaf(v, d.x, acc.x);
        acc.y = fmaf(v, d.y, acc.y);
        acc.z = fmaf(v, d.z, acc.z);
        acc.w = fmaf(v, d.w, acc.w);
    }
    if (EPI) {
        float4 b = ((const float4*)bias)[lane];
        acc.x = fmaxf(acc.x + b.x, 0.f);
        acc.y = fmaxf(acc.y + b.y, 0.f);
        acc.z = fmaxf(acc.z + b.z, 0.f);
        acc.w = fmaxf(acc.w + b.w, 0.f);
    }
    ((float4*)(out + (size_t)warp * HID))[lane] = acc;
}

// ------------------------------ launch --------------------------------------
extern "C" void kernel_launch(void* const* d_in, const int* in_sizes, int n_in,
                              void* d_out, int out_size) {
    const float* x           = (const float*)d_in[0];
    const int*   adj_row     = (const int*)d_in[1];
    const int*   adj_col     = (const int*)d_in[2];
    const float* adj_val     = (const float*)d_in[3];
    const int*   adj_inv_row = (const int*)d_in[4];
    const int*   adj_inv_col = (const int*)d_in[5];
    const float* adj_inv_val = (const float*)d_in[6];
    const float* W1          = (const float*)d_in[7];
    const float* b1          = (const float*)d_in[8];
    const float* W2          = (const float*)d_in[9];
    const float* b2          = (const float*)d_in[10];

    float* out = (float*)d_out;                   // [N, NFEAT]
    float* h   = out + (size_t)NROWS * NFEAT;     // [N, HID]

    float *xw, *val1, *val2;
    __nv_bfloat16 *bh1, *bl1, *bh2, *bl2;
    int *col1, *rs1, *col2, *rs2, *cnt, *next;
    cudaGetSymbolAddress((void**)&xw,   g_xw);
    cudaGetSymbolAddress((void**)&bh1,  g_bh1);
    cudaGetSymbolAddress((void**)&bl1,  g_bl1);
    cudaGetSymbolAddress((void**)&bh2,  g_bh2);
    cudaGetSymbolAddress((void**)&bl2,  g_bl2);
    cudaGetSymbolAddress((void**)&col1, g_col1);
    cudaGetSymbolAddress((void**)&val1, g_val1);
    cudaGetSymbolAddress((void**)&rs1,  g_rs1);
    cudaGetSymbolAddress((void**)&col2, g_col2);
    cudaGetSymbolAddress((void**)&val2, g_val2);
    cudaGetSymbolAddress((void**)&rs2,  g_rs2);
    cudaGetSymbolAddress((void**)&cnt,  g_cnt);
    cudaGetSymbolAddress((void**)&next, g_next);

    cudaFuncSetAttribute(k_gemm_f<false>,
                         cudaFuncAttributeMaxDynamicSharedMemorySize, GSMEM2);
    cudaFuncSetAttribute(k_gemm_f<true>,
                         cudaFuncAttributeMaxDynamicSharedMemorySize, GSMEM2);

    const int TB = 256;
    const int g2N = (2 * NROWS + TB - 1) / TB;
    const int g2E = (int)((2L * NEDGE + TB - 1) / TB);

    // --- weight splits (independent, tiny) ---
    k_splitw2<<<(NFEAT * HID + TB - 1) / TB, TB>>>(W1, bh1, bl1, NFEAT, HID);
    k_splitw2<<<(HID * NFEAT + TB - 1) / TB, TB>>>(W2, bh2, bl2, HID, NFEAT);

    // --- CSR build (both graphs fused) ---
    k_zero2<<<g2N, TB>>>(cnt);
    k_hist2<<<g2E, TB>>>(adj_row, adj_inv_row, cnt);
    k_scan2<<<2, 1024>>>(cnt, rs1, rs2, next);
    k_scatter2<<<g2E, TB>>>(adj_row, adj_col, adj_val,
                            adj_inv_row, adj_inv_col, adj_inv_val,
                            next, col1, val1, col2, val2);

    // --- layer 1: xw = x @ W1 ; h = relu(A1 @ xw + b1) ---
    {
        dim3 grid(MPAD / 128, HID / 128);
        k_gemm_f<false><<<grid, 256, GSMEM2>>>(x, bh1, bl1, xw, NROWS, HID, NFEAT, nullptr);
    }
    k_spmm_d128<true><<<(NROWS * 32 + TB - 1) / TB, TB>>>(rs1, col1, val1, xw, b1, h);

    // --- layer 2 (re-associated): g = A2 @ h ; out = relu(g @ W2 + b2) ---
    k_spmm_d128<false><<<(NROWS * 32 + TB - 1) / TB, TB>>>(rs2, col2, val2, h, nullptr, xw);
    {
        dim3 grid(MPAD / 128, NFEAT / 128);
        k_gemm_f<true><<<grid, 256, GSMEM2>>>(xw, bh2, bl2, out, NROWS, NFEAT, HID, b2);
    }
}